// round 10
// baseline (speedup 1.0000x reference)
#include <cuda_runtime.h>

// ---------------------------------------------------------------------------
// Problem constants (hardcoded from the reference: B=2, NH=4, T=8, H=14, W=14)
// ---------------------------------------------------------------------------
#define BQ   2
#define NHD  4
#define TT   8
#define HH   14
#define WW   14
#define NTOK 1568          // T*H*W
#define DIMV 384
#define HD   96
#define BH   8             // BQ*NHD
#define SCALE 0.10206207261596575f   // 96^-0.5

// ---------------------------------------------------------------------------
// Scratch (no allocation allowed -> __device__ globals)
// ---------------------------------------------------------------------------
__device__ float g_q0[BH * NTOK * HD];
__device__ float g_k0[BH * NTOK * HD];
__device__ float g_v0[BH * NTOK * HD];
__device__ float g_qp[BH * NTOK * HD];
__device__ float g_kp[BH * NTOK * HD];
__device__ float g_vp[BH * NTOK * HD];
__device__ float g_relh[BH * NTOK * 14];
__device__ float g_relw[BH * NTOK * 14];
__device__ float g_relt[BH * NTOK * 8];
__device__ float g_ctx[BQ * NTOK * DIMV];   // [B][N][NH][HD]

// ---------------------------------------------------------------------------
// K1 / K5: SGEMM  C[M,Nn] = A[M,K] @ Bw[Nn,K]^T   (both K-contiguous)
// MODE 0: A = x, scatter into g_q0/g_k0/g_v0
// MODE 1: A = g_ctx (internal), C = out, add bias
// BM=BN=128, BK=16, 256 threads, 8x8 microtile
// ---------------------------------------------------------------------------
#define GBM 128
#define GBN 128
#define GBK 16
#define SAS 132   // padded smem row stride

template <int MODE>
__global__ void __launch_bounds__(256) sgemm_kernel(
    const float* __restrict__ A, const float* __restrict__ Bw,
    const float* __restrict__ bias, float* __restrict__ C,
    int M, int Nn, int K)
{
    __shared__ float As[GBK][SAS];
    __shared__ float Bs[GBK][SAS];

    const int tid = threadIdx.x;
    const int tx = tid & 15, ty = tid >> 4;
    const int mb = blockIdx.x * GBM, nb = blockIdx.y * GBN;

    if (MODE == 1) A = g_ctx;

    float acc[8][8];
#pragma unroll
    for (int i = 0; i < 8; i++)
#pragma unroll
        for (int j = 0; j < 8; j++) acc[i][j] = 0.f;

    for (int kt = 0; kt < K; kt += GBK) {
#pragma unroll
        for (int it = 0; it < 2; it++) {
            int f = tid + it * 256;          // float4 index within tile
            int m = f >> 2;
            int k0 = (f & 3) * 4;
            float4 a = make_float4(0.f, 0.f, 0.f, 0.f);
            int gm = mb + m;
            if (gm < M) a = *(const float4*)(A + (size_t)gm * K + kt + k0);
            As[k0 + 0][m] = a.x; As[k0 + 1][m] = a.y;
            As[k0 + 2][m] = a.z; As[k0 + 3][m] = a.w;
            float4 b = make_float4(0.f, 0.f, 0.f, 0.f);
            int gn = nb + m;
            if (gn < Nn) b = *(const float4*)(Bw + (size_t)gn * K + kt + k0);
            Bs[k0 + 0][m] = b.x; Bs[k0 + 1][m] = b.y;
            Bs[k0 + 2][m] = b.z; Bs[k0 + 3][m] = b.w;
        }
        __syncthreads();

#pragma unroll
        for (int kk = 0; kk < GBK; kk++) {
            float ar[8], br[8];
            *(float4*)(ar)     = *(const float4*)&As[kk][ty * 8];
            *(float4*)(ar + 4) = *(const float4*)&As[kk][ty * 8 + 4];
            *(float4*)(br)     = *(const float4*)&Bs[kk][tx * 8];
            *(float4*)(br + 4) = *(const float4*)&Bs[kk][tx * 8 + 4];
#pragma unroll
            for (int i = 0; i < 8; i++)
#pragma unroll
                for (int j = 0; j < 8; j++) acc[i][j] += ar[i] * br[j];
        }
        __syncthreads();
    }

#pragma unroll
    for (int i = 0; i < 8; i++) {
        int gm = mb + ty * 8 + i;
        if (gm >= M) continue;
        if (MODE == 0) {
            int b = gm / NTOK, n = gm % NTOK;
#pragma unroll
            for (int jj = 0; jj < 8; jj++) {
                int j = nb + tx * 8 + jj;
                int s = j / DIMV;
                int r = j - s * DIMV;
                int head = r / HD;
                int c = r - head * HD;
                float* dst = (s == 0) ? g_q0 : (s == 1) ? g_k0 : g_v0;
                dst[((size_t)(b * NHD + head) * NTOK + n) * HD + c] = acc[i][jj];
            }
        } else {
#pragma unroll
            for (int jj = 0; jj < 8; jj++) {
                int j = nb + tx * 8 + jj;
                C[(size_t)gm * Nn + j] = acc[i][jj] + bias[j];
            }
        }
    }
}

// ---------------------------------------------------------------------------
// K2: depthwise conv3d (3x3x3, pad 1, cross-correlation) + LayerNorm over HD
// grid: (BH*NTOK, 3 [q,k,v]), block: 96 threads (one per channel)
// ---------------------------------------------------------------------------
__global__ void __launch_bounds__(96) pool_ln_kernel(
    const float* __restrict__ pw0, const float* __restrict__ pw1, const float* __restrict__ pw2,
    const float* __restrict__ nw0, const float* __restrict__ nb0,
    const float* __restrict__ nw1, const float* __restrict__ nb1,
    const float* __restrict__ nw2, const float* __restrict__ nb2)
{
    const int which = blockIdx.y;
    const float* src = (which == 0) ? g_q0 : (which == 1) ? g_k0 : g_v0;
    float* dst       = (which == 0) ? g_qp : (which == 1) ? g_kp : g_vp;
    const float* pw  = (which == 0) ? pw0 : (which == 1) ? pw1 : pw2;
    const float* nw  = (which == 0) ? nw0 : (which == 1) ? nw1 : nw2;
    const float* nb  = (which == 0) ? nb0 : (which == 1) ? nb1 : nb2;

    const int idx = blockIdx.x;            // bh*NTOK + n
    const int n = idx % NTOK;
    const int t = n / (HH * WW);
    const int hw = n - t * (HH * WW);
    const int h = hw / WW;
    const int w = hw - h * WW;
    const int c = threadIdx.x;

    const float* base = src + (size_t)(idx - n) * HD;   // (bh*NTOK)*HD

    float wreg[27];
#pragma unroll
    for (int j = 0; j < 27; j++) wreg[j] = pw[c * 27 + j];

    float s = 0.f;
#pragma unroll
    for (int dt = 0; dt < 3; dt++) {
        int tt = t + dt - 1;
        if (tt < 0 || tt >= TT) continue;
#pragma unroll
        for (int dh = 0; dh < 3; dh++) {
            int hh = h + dh - 1;
            if (hh < 0 || hh >= HH) continue;
#pragma unroll
            for (int dw = 0; dw < 3; dw++) {
                int ww = w + dw - 1;
                if (ww < 0 || ww >= WW) continue;
                s += wreg[dt * 9 + dh * 3 + dw] *
                     base[(size_t)(tt * (HH * WW) + hh * WW + ww) * HD + c];
            }
        }
    }

    __shared__ float red[6];
    const int wid = threadIdx.x >> 5, lane = threadIdx.x & 31;
    float v = s;
#pragma unroll
    for (int off = 16; off; off >>= 1) v += __shfl_xor_sync(0xffffffffu, v, off);
    if (!lane) red[wid] = v;
    __syncthreads();
    float mean = (red[0] + red[1] + red[2]) * (1.f / 96.f);
    float d = s - mean;
    float v2 = d * d;
#pragma unroll
    for (int off = 16; off; off >>= 1) v2 += __shfl_xor_sync(0xffffffffu, v2, off);
    if (!lane) red[3 + wid] = v2;
    __syncthreads();
    float var = (red[3] + red[4] + red[5]) * (1.f / 96.f);

    dst[(size_t)idx * HD + c] = d * rsqrtf(var + 1e-6f) * nw[c] + nb[c];
}

// ---------------------------------------------------------------------------
// K3: rel-pos bias dots:  rel_h[idx][kh] = q(idx) . rel_pos_h[h-kh+13], etc.
// grid: BH*NTOK blocks, 128 threads (4 warps, 9 dots each)
// ---------------------------------------------------------------------------
__global__ void __launch_bounds__(128) relbias_kernel(
    const float* __restrict__ rph, const float* __restrict__ rpw,
    const float* __restrict__ rpt)
{
    const int idx = blockIdx.x;
    const int n = idx % NTOK;
    const int t = n / (HH * WW);
    const int hw = n - t * (HH * WW);
    const int h = hw / WW;
    const int w = hw - h * WW;

    __shared__ float qs[96];
    if (threadIdx.x < 96) qs[threadIdx.x] = g_qp[(size_t)idx * HD + threadIdx.x];
    __syncthreads();

    const int wid = threadIdx.x >> 5, lane = threadIdx.x & 31;
    for (int r = wid; r < 36; r += 4) {
        const float* tab;
        float* dst;
        if (r < 14) {
            tab = rph + (size_t)(h - r + 13) * HD;
            dst = g_relh + (size_t)idx * 14 + r;
        } else if (r < 28) {
            int kw = r - 14;
            tab = rpw + (size_t)(w - kw + 13) * HD;
            dst = g_relw + (size_t)idx * 14 + kw;
        } else {
            int kt = r - 28;
            tab = rpt + (size_t)(t - kt + 7) * HD;
            dst = g_relt + (size_t)idx * 8 + kt;
        }
        float p = 0.f;
        for (int c = lane; c < 96; c += 32) p += qs[c] * tab[c];
#pragma unroll
        for (int off = 16; off; off >>= 1) p += __shfl_xor_sync(0xffffffffu, p, off);
        if (!lane) *dst = p;
    }
}

// ---------------------------------------------------------------------------
// K4: flash attention, TQ=32, TK=64, 256 threads, online softmax
// + decomposed rel-pos bias, fused residual (+pooled q) into g_ctx
// ---------------------------------------------------------------------------
#define TQ 32
#define TK 64
// smem layout (floats)
#define SQ_OFF 0                 // Qs_t [96][32]
#define SK_OFF (SQ_OFF + 96*32)  // Ks_t [96][64]
#define SV_OFF (SK_OFF + 96*64)  // Vs   [64][100]
#define SP_OFF (SV_OFF + 64*100) // Ps   [32][68]
#define SBH_OFF (SP_OFF + 32*68) // [32][14]
#define SBW_OFF (SBH_OFF + 32*14)
#define SBT_OFF (SBW_OFF + 32*14) // [32][8]
#define SKI_OFF (SBT_OFF + 32*8)  // int kt[64], kh[64], kw[64]
#define ATTN_SMEM_FLOATS (SKI_OFF + 3*64)
#define ATTN_SMEM_BYTES (ATTN_SMEM_FLOATS * 4)

__global__ void __launch_bounds__(256, 3) attn_kernel()
{
    extern __shared__ float sm[];
    float* Qs  = sm + SQ_OFF;
    float* Ks  = sm + SK_OFF;
    float* Vs  = sm + SV_OFF;
    float* Ps  = sm + SP_OFF;
    float* bhs = sm + SBH_OFF;
    float* bws = sm + SBW_OFF;
    float* bts = sm + SBT_OFF;
    int*   kti = (int*)(sm + SKI_OFF);
    int*   khi = kti + 64;
    int*   kwi = khi + 64;

    const int bh = blockIdx.y;
    const int qbase = blockIdx.x * TQ;
    const int tid = threadIdx.x;
    const int tx = tid & 15, ty = tid >> 4;
    const int r0 = ty * 2;       // 2 q rows per thread
    const int c0 = tx * 4;       // 4 score cols per thread (GEMM1)
    const int vc = tx * 6;       // 6 out cols per thread (GEMM2)

    const float* qptr = g_qp + (size_t)bh * NTOK * HD;
    const float* kptr = g_kp + (size_t)bh * NTOK * HD;
    const float* vptr = g_vp + (size_t)bh * NTOK * HD;

    // ---- load Q tile (transposed, pre-scaled) ----
    {
        int r = tid & 31;
        int cg = tid >> 5;        // 0..7 -> 12 cols
        const float* src = qptr + (size_t)(qbase + r) * HD + cg * 12;
#pragma unroll
        for (int j = 0; j < 3; j++) {
            float4 v = *(const float4*)(src + j * 4);
            int c = cg * 12 + j * 4;
            Qs[(c + 0) * 32 + r] = v.x * SCALE;
            Qs[(c + 1) * 32 + r] = v.y * SCALE;
            Qs[(c + 2) * 32 + r] = v.z * SCALE;
            Qs[(c + 3) * 32 + r] = v.w * SCALE;
        }
    }
    // ---- load bias tables for the 32 q rows ----
    for (int i = tid; i < 32 * 14; i += 256) {
        int r = i / 14, kh = i - r * 14;
        size_t base = ((size_t)bh * NTOK + qbase + r);
        bhs[i] = g_relh[base * 14 + kh];
        bws[i] = g_relw[base * 14 + kh];
    }
    if (tid < 32 * 8) {
        int r = tid >> 3, kt = tid & 7;
        bts[tid] = g_relt[((size_t)bh * NTOK + qbase + r) * 8 + kt];
    }

    float m[2] = {-1e30f, -1e30f};
    float l[2] = {0.f, 0.f};
    float o[2][6];
#pragma unroll
    for (int j = 0; j < 2; j++)
#pragma unroll
        for (int i = 0; i < 6; i++) o[j][i] = 0.f;

    for (int kc = 0; kc < 25; kc++) {
        const int kb = kc * TK;
        __syncthreads();   // protect Ks/Vs/Ps from previous iteration readers

        // ---- load K tile (transposed) and V tile ----
        {
            int r = tid & 63;
            int cg = tid >> 6;    // 0..3 -> 24 cols
            int gk = kb + r;
            bool ok = gk < NTOK;
            const float* ks = kptr + (size_t)gk * HD + cg * 24;
            const float* vs = vptr + (size_t)gk * HD + cg * 24;
#pragma unroll
            for (int j = 0; j < 6; j++) {
                int c = cg * 24 + j * 4;
                float4 a = ok ? *(const float4*)(ks + j * 4) : make_float4(0,0,0,0);
                Ks[(c + 0) * 64 + r] = a.x;
                Ks[(c + 1) * 64 + r] = a.y;
                Ks[(c + 2) * 64 + r] = a.z;
                Ks[(c + 3) * 64 + r] = a.w;
                float4 b = ok ? *(const float4*)(vs + j * 4) : make_float4(0,0,0,0);
                *(float4*)&Vs[r * 100 + c] = b;
            }
            if (tid < 64) {
                int gk2 = kb + tid;
                int kt = gk2 / (HH * WW); if (kt > TT - 1) kt = TT - 1;
                int rem = gk2 - kt * (HH * WW);
                kti[tid] = kt;
                khi[tid] = rem / WW < HH ? rem / WW : HH - 1;
                kwi[tid] = rem % WW;
            }
        }
        __syncthreads();

        // ---- GEMM1: S = Qs^T-scaled @ K ----
        float acc[2][4];
#pragma unroll
        for (int j = 0; j < 2; j++)
#pragma unroll
            for (int i = 0; i < 4; i++) acc[j][i] = 0.f;
#pragma unroll 8
        for (int kk = 0; kk < 96; kk++) {
            float2 a = *(const float2*)&Qs[kk * 32 + r0];
            float4 b = *(const float4*)&Ks[kk * 64 + c0];
            acc[0][0] += a.x * b.x; acc[0][1] += a.x * b.y;
            acc[0][2] += a.x * b.z; acc[0][3] += a.x * b.w;
            acc[1][0] += a.y * b.x; acc[1][1] += a.y * b.y;
            acc[1][2] += a.y * b.z; acc[1][3] += a.y * b.w;
        }

        // ---- bias + online softmax ----
        float p[2][4];
        float cm[2] = {-1e30f, -1e30f};
#pragma unroll
        for (int i = 0; i < 4; i++) {
            int cc = c0 + i;
            int gk = kb + cc;
            float bt0 = bts[r0 * 8 + kti[cc]]       + bhs[r0 * 14 + khi[cc]]       + bws[r0 * 14 + kwi[cc]];
            float bt1 = bts[(r0 + 1) * 8 + kti[cc]] + bhs[(r0 + 1) * 14 + khi[cc]] + bws[(r0 + 1) * 14 + kwi[cc]];
            float s0 = acc[0][i] + bt0;
            float s1 = acc[1][i] + bt1;
            if (gk >= NTOK) { s0 = -1e30f; s1 = -1e30f; }
            p[0][i] = s0; p[1][i] = s1;
            cm[0] = fmaxf(cm[0], s0);
            cm[1] = fmaxf(cm[1], s1);
        }
#pragma unroll
        for (int off = 1; off < 16; off <<= 1) {
            cm[0] = fmaxf(cm[0], __shfl_xor_sync(0xffffffffu, cm[0], off));
            cm[1] = fmaxf(cm[1], __shfl_xor_sync(0xffffffffu, cm[1], off));
        }
        float rs[2] = {0.f, 0.f};
#pragma unroll
        for (int j = 0; j < 2; j++) {
            float mn = fmaxf(m[j], cm[j]);
            float f = __expf(m[j] - mn);
            m[j] = mn;
#pragma unroll
            for (int i = 0; i < 4; i++) {
                p[j][i] = __expf(p[j][i] - mn);
                rs[j] += p[j][i];
            }
            l[j] *= f;
#pragma unroll
            for (int i = 0; i < 6; i++) o[j][i] *= f;
        }
#pragma unroll
        for (int off = 1; off < 16; off <<= 1) {
            rs[0] += __shfl_xor_sync(0xffffffffu, rs[0], off);
            rs[1] += __shfl_xor_sync(0xffffffffu, rs[1], off);
        }
        l[0] += rs[0]; l[1] += rs[1];

        *(float4*)&Ps[r0 * 68 + c0]       = make_float4(p[0][0], p[0][1], p[0][2], p[0][3]);
        *(float4*)&Ps[(r0 + 1) * 68 + c0] = make_float4(p[1][0], p[1][1], p[1][2], p[1][3]);
        __syncthreads();

        // ---- GEMM2: O += P @ V ----
#pragma unroll 8
        for (int kk = 0; kk < TK; kk++) {
            float p0 = Ps[r0 * 68 + kk];
            float p1 = Ps[(r0 + 1) * 68 + kk];
            const float* vrow = &Vs[kk * 100 + vc];
            float2 va = *(const float2*)(vrow);
            float2 vb = *(const float2*)(vrow + 2);
            float2 vx = *(const float2*)(vrow + 4);
            o[0][0] += p0 * va.x; o[0][1] += p0 * va.y;
            o[0][2] += p0 * vb.x; o[0][3] += p0 * vb.y;
            o[0][4] += p0 * vx.x; o[0][5] += p0 * vx.y;
            o[1][0] += p1 * va.x; o[1][1] += p1 * va.y;
            o[1][2] += p1 * vb.x; o[1][3] += p1 * vb.y;
            o[1][4] += p1 * vx.x; o[1][5] += p1 * vx.y;
        }
    }

    // ---- epilogue: /l, + residual pooled q, scatter to [B][N][NH][HD] ----
    const int b = bh >> 2, head = bh & 3;
#pragma unroll
    for (int j = 0; j < 2; j++) {
        int qn = qbase + r0 + j;
        float inv = 1.0f / l[j];
        float* dst = g_ctx + (((size_t)(b * NTOK + qn)) * NHD + head) * HD + vc;
        const float* qr = qptr + (size_t)qn * HD + vc;
#pragma unroll
        for (int i = 0; i < 6; i++) dst[i] = o[j][i] * inv + qr[i];
    }
}

// ---------------------------------------------------------------------------
// launch
// ---------------------------------------------------------------------------
extern "C" void kernel_launch(void* const* d_in, const int* in_sizes, int n_in,
                              void* d_out, int out_size)
{
    (void)in_sizes; (void)n_in; (void)out_size;
    const float* x      = (const float*)d_in[0];
    const float* qkv_w  = (const float*)d_in[1];
    const float* proj_w = (const float*)d_in[2];
    const float* proj_b = (const float*)d_in[3];
    const float* pqw    = (const float*)d_in[4];
    const float* pkw    = (const float*)d_in[5];
    const float* pvw    = (const float*)d_in[6];
    const float* nqw    = (const float*)d_in[7];
    const float* nqb    = (const float*)d_in[8];
    const float* nkw    = (const float*)d_in[9];
    const float* nkb    = (const float*)d_in[10];
    const float* nvw    = (const float*)d_in[11];
    const float* nvb    = (const float*)d_in[12];
    const float* rph    = (const float*)d_in[13];
    const float* rpw    = (const float*)d_in[14];
    const float* rpt    = (const float*)d_in[15];
    float* out = (float*)d_out;

    cudaFuncSetAttribute(attn_kernel, cudaFuncAttributeMaxDynamicSharedMemorySize,
                         ATTN_SMEM_BYTES);

    const int M = BQ * NTOK;  // 3136
    // K1: QKV projection, scatter to q0/k0/v0
    sgemm_kernel<0><<<dim3((M + GBM - 1) / GBM, (3 * DIMV) / GBN), 256>>>(
        x, qkv_w, nullptr, nullptr, M, 3 * DIMV, DIMV);
    // K2: depthwise conv3d + LN for q, k, v
    pool_ln_kernel<<<dim3(BH * NTOK, 3), 96>>>(pqw, pkw, pvw,
                                               nqw, nqb, nkw, nkb, nvw, nvb);
    // K3: rel-pos bias dots
    relbias_kernel<<<BH * NTOK, 128>>>(rph, rpw, rpt);
    // K4: flash attention with bias + residual
    attn_kernel<<<dim3(NTOK / TQ, BH), 256, ATTN_SMEM_BYTES>>>();
    // K5: output projection
    sgemm_kernel<1><<<dim3((M + GBM - 1) / GBM, DIMV / GBN), 256>>>(
        nullptr, proj_w, proj_b, out, M, DIMV, DIMV);
}

// round 11
// speedup vs baseline: 1.0522x; 1.0522x over previous
#include <cuda_runtime.h>

// ---------------------------------------------------------------------------
// Problem constants (hardcoded from the reference: B=2, NH=4, T=8, H=14, W=14)
// ---------------------------------------------------------------------------
#define BQ   2
#define NHD  4
#define TT   8
#define HH   14
#define WW   14
#define NTOK 1568          // T*H*W
#define DIMV 384
#define HD   96
#define BH   8             // BQ*NHD
#define SCALE 0.10206207261596575f   // 96^-0.5

// ---------------------------------------------------------------------------
// Scratch (no allocation allowed -> __device__ globals)
// ---------------------------------------------------------------------------
__device__ float g_q0[BH * NTOK * HD];
__device__ float g_k0[BH * NTOK * HD];
__device__ float g_v0[BH * NTOK * HD];
__device__ float g_qp[BH * NTOK * HD];
__device__ float g_kp[BH * NTOK * HD];
__device__ float g_vp[BH * NTOK * HD];
__device__ float g_relh[BH * NTOK * 14];
__device__ float g_relw[BH * NTOK * 14];
__device__ float g_relt[BH * NTOK * 8];
__device__ float g_ctx[BQ * NTOK * DIMV];   // [B][N][NH][HD]

// ---------------------------------------------------------------------------
// K1 / K5: SGEMM  C[M,Nn] = A[M,K] @ Bw[Nn,K]^T   (both K-contiguous)
// MODE 0: A = x, scatter into g_q0/g_k0/g_v0
// MODE 1: A = g_ctx (internal), C = out, add bias
// BM=BN=128, BK=16, 256 threads, 8x8 microtile
// ---------------------------------------------------------------------------
#define GBM 128
#define GBN 128
#define GBK 16
#define SAS 132   // padded smem row stride

template <int MODE>
__global__ void __launch_bounds__(256) sgemm_kernel(
    const float* __restrict__ A, const float* __restrict__ Bw,
    const float* __restrict__ bias, float* __restrict__ C,
    int M, int Nn, int K)
{
    __shared__ float As[GBK][SAS];
    __shared__ float Bs[GBK][SAS];

    const int tid = threadIdx.x;
    const int tx = tid & 15, ty = tid >> 4;
    const int mb = blockIdx.x * GBM, nb = blockIdx.y * GBN;

    if (MODE == 1) A = g_ctx;

    float acc[8][8];
#pragma unroll
    for (int i = 0; i < 8; i++)
#pragma unroll
        for (int j = 0; j < 8; j++) acc[i][j] = 0.f;

    for (int kt = 0; kt < K; kt += GBK) {
#pragma unroll
        for (int it = 0; it < 2; it++) {
            int f = tid + it * 256;          // float4 index within tile
            int m = f >> 2;
            int k0 = (f & 3) * 4;
            float4 a = make_float4(0.f, 0.f, 0.f, 0.f);
            int gm = mb + m;
            if (gm < M) a = *(const float4*)(A + (size_t)gm * K + kt + k0);
            As[k0 + 0][m] = a.x; As[k0 + 1][m] = a.y;
            As[k0 + 2][m] = a.z; As[k0 + 3][m] = a.w;
            float4 b = make_float4(0.f, 0.f, 0.f, 0.f);
            int gn = nb + m;
            if (gn < Nn) b = *(const float4*)(Bw + (size_t)gn * K + kt + k0);
            Bs[k0 + 0][m] = b.x; Bs[k0 + 1][m] = b.y;
            Bs[k0 + 2][m] = b.z; Bs[k0 + 3][m] = b.w;
        }
        __syncthreads();

#pragma unroll
        for (int kk = 0; kk < GBK; kk++) {
            float ar[8], br[8];
            *(float4*)(ar)     = *(const float4*)&As[kk][ty * 8];
            *(float4*)(ar + 4) = *(const float4*)&As[kk][ty * 8 + 4];
            *(float4*)(br)     = *(const float4*)&Bs[kk][tx * 8];
            *(float4*)(br + 4) = *(const float4*)&Bs[kk][tx * 8 + 4];
#pragma unroll
            for (int i = 0; i < 8; i++)
#pragma unroll
                for (int j = 0; j < 8; j++) acc[i][j] += ar[i] * br[j];
        }
        __syncthreads();
    }

#pragma unroll
    for (int i = 0; i < 8; i++) {
        int gm = mb + ty * 8 + i;
        if (gm >= M) continue;
        if (MODE == 0) {
            int b = gm / NTOK, n = gm % NTOK;
#pragma unroll
            for (int jj = 0; jj < 8; jj++) {
                int j = nb + tx * 8 + jj;
                int s = j / DIMV;
                int r = j - s * DIMV;
                int head = r / HD;
                int c = r - head * HD;
                float* dst = (s == 0) ? g_q0 : (s == 1) ? g_k0 : g_v0;
                dst[((size_t)(b * NHD + head) * NTOK + n) * HD + c] = acc[i][jj];
            }
        } else {
#pragma unroll
            for (int jj = 0; jj < 8; jj++) {
                int j = nb + tx * 8 + jj;
                C[(size_t)gm * Nn + j] = acc[i][jj] + bias[j];
            }
        }
    }
}

// ---------------------------------------------------------------------------
// K2: depthwise conv3d (3x3x3, pad 1, cross-correlation) + LayerNorm over HD
// grid: (BH*NTOK, 3 [q,k,v]), block: 96 threads (one per channel)
// ---------------------------------------------------------------------------
__global__ void __launch_bounds__(96) pool_ln_kernel(
    const float* __restrict__ pw0, const float* __restrict__ pw1, const float* __restrict__ pw2,
    const float* __restrict__ nw0, const float* __restrict__ nb0,
    const float* __restrict__ nw1, const float* __restrict__ nb1,
    const float* __restrict__ nw2, const float* __restrict__ nb2)
{
    const int which = blockIdx.y;
    const float* src = (which == 0) ? g_q0 : (which == 1) ? g_k0 : g_v0;
    float* dst       = (which == 0) ? g_qp : (which == 1) ? g_kp : g_vp;
    const float* pw  = (which == 0) ? pw0 : (which == 1) ? pw1 : pw2;
    const float* nw  = (which == 0) ? nw0 : (which == 1) ? nw1 : nw2;
    const float* nb  = (which == 0) ? nb0 : (which == 1) ? nb1 : nb2;

    const int idx = blockIdx.x;            // bh*NTOK + n
    const int n = idx % NTOK;
    const int t = n / (HH * WW);
    const int hw = n - t * (HH * WW);
    const int h = hw / WW;
    const int w = hw - h * WW;
    const int c = threadIdx.x;

    const float* base = src + (size_t)(idx - n) * HD;   // (bh*NTOK)*HD

    float wreg[27];
#pragma unroll
    for (int j = 0; j < 27; j++) wreg[j] = pw[c * 27 + j];

    float s = 0.f;
#pragma unroll
    for (int dt = 0; dt < 3; dt++) {
        int tt = t + dt - 1;
        if (tt < 0 || tt >= TT) continue;
#pragma unroll
        for (int dh = 0; dh < 3; dh++) {
            int hh = h + dh - 1;
            if (hh < 0 || hh >= HH) continue;
#pragma unroll
            for (int dw = 0; dw < 3; dw++) {
                int ww = w + dw - 1;
                if (ww < 0 || ww >= WW) continue;
                s += wreg[dt * 9 + dh * 3 + dw] *
                     base[(size_t)(tt * (HH * WW) + hh * WW + ww) * HD + c];
            }
        }
    }

    __shared__ float red[6];
    const int wid = threadIdx.x >> 5, lane = threadIdx.x & 31;
    float v = s;
#pragma unroll
    for (int off = 16; off; off >>= 1) v += __shfl_xor_sync(0xffffffffu, v, off);
    if (!lane) red[wid] = v;
    __syncthreads();
    float mean = (red[0] + red[1] + red[2]) * (1.f / 96.f);
    float d = s - mean;
    float v2 = d * d;
#pragma unroll
    for (int off = 16; off; off >>= 1) v2 += __shfl_xor_sync(0xffffffffu, v2, off);
    if (!lane) red[3 + wid] = v2;
    __syncthreads();
    float var = (red[3] + red[4] + red[5]) * (1.f / 96.f);

    dst[(size_t)idx * HD + c] = d * rsqrtf(var + 1e-6f) * nw[c] + nb[c];
}

// ---------------------------------------------------------------------------
// K3: rel-pos bias dots:  rel_h[idx][kh] = q(idx) . rel_pos_h[h-kh+13], etc.
// grid: BH*NTOK blocks, 128 threads (4 warps, 9 dots each)
// ---------------------------------------------------------------------------
__global__ void __launch_bounds__(128) relbias_kernel(
    const float* __restrict__ rph, const float* __restrict__ rpw,
    const float* __restrict__ rpt)
{
    const int idx = blockIdx.x;
    const int n = idx % NTOK;
    const int t = n / (HH * WW);
    const int hw = n - t * (HH * WW);
    const int h = hw / WW;
    const int w = hw - h * WW;

    __shared__ float qs[96];
    if (threadIdx.x < 96) qs[threadIdx.x] = g_qp[(size_t)idx * HD + threadIdx.x];
    __syncthreads();

    const int wid = threadIdx.x >> 5, lane = threadIdx.x & 31;
    for (int r = wid; r < 36; r += 4) {
        const float* tab;
        float* dst;
        if (r < 14) {
            tab = rph + (size_t)(h - r + 13) * HD;
            dst = g_relh + (size_t)idx * 14 + r;
        } else if (r < 28) {
            int kw = r - 14;
            tab = rpw + (size_t)(w - kw + 13) * HD;
            dst = g_relw + (size_t)idx * 14 + kw;
        } else {
            int kt = r - 28;
            tab = rpt + (size_t)(t - kt + 7) * HD;
            dst = g_relt + (size_t)idx * 8 + kt;
        }
        float p = 0.f;
        for (int c = lane; c < 96; c += 32) p += qs[c] * tab[c];
#pragma unroll
        for (int off = 16; off; off >>= 1) p += __shfl_xor_sync(0xffffffffu, p, off);
        if (!lane) *dst = p;
    }
}

// ---------------------------------------------------------------------------
// K4: flash attention, TQ=32, TK=64, 256 threads, online softmax
// + decomposed rel-pos bias, fused residual (+pooled q) into g_ctx
// ---------------------------------------------------------------------------
#define TQ 32
#define TK 64
// smem layout (floats)
#define SQ_OFF 0                 // Qs_t [96][32]
#define SK_OFF (SQ_OFF + 96*32)  // Ks_t [96][64]
#define SV_OFF (SK_OFF + 96*64)  // Vs   [64][100]
#define SP_OFF (SV_OFF + 64*100) // Ps   [32][68]
#define SBH_OFF (SP_OFF + 32*68) // [32][14]
#define SBW_OFF (SBH_OFF + 32*14)
#define SBT_OFF (SBW_OFF + 32*14) // [32][8]
#define SKI_OFF (SBT_OFF + 32*8)  // int kt[64], kh[64], kw[64]
#define ATTN_SMEM_FLOATS (SKI_OFF + 3*64)
#define ATTN_SMEM_BYTES (ATTN_SMEM_FLOATS * 4)

__global__ void __launch_bounds__(256, 3) attn_kernel()
{
    extern __shared__ float sm[];
    float* Qs  = sm + SQ_OFF;
    float* Ks  = sm + SK_OFF;
    float* Vs  = sm + SV_OFF;
    float* Ps  = sm + SP_OFF;
    float* bhs = sm + SBH_OFF;
    float* bws = sm + SBW_OFF;
    float* bts = sm + SBT_OFF;
    int*   kti = (int*)(sm + SKI_OFF);
    int*   khi = kti + 64;
    int*   kwi = khi + 64;

    const int bh = blockIdx.y;
    const int qbase = blockIdx.x * TQ;
    const int tid = threadIdx.x;
    const int tx = tid & 15, ty = tid >> 4;
    const int r0 = ty * 2;       // 2 q rows per thread
    const int c0 = tx * 4;       // 4 score cols per thread (GEMM1)
    const int vc = tx * 6;       // 6 out cols per thread (GEMM2)

    const float* qptr = g_qp + (size_t)bh * NTOK * HD;
    const float* kptr = g_kp + (size_t)bh * NTOK * HD;
    const float* vptr = g_vp + (size_t)bh * NTOK * HD;

    // ---- load Q tile (transposed, pre-scaled) ----
    {
        int r = tid & 31;
        int cg = tid >> 5;        // 0..7 -> 12 cols
        const float* src = qptr + (size_t)(qbase + r) * HD + cg * 12;
#pragma unroll
        for (int j = 0; j < 3; j++) {
            float4 v = *(const float4*)(src + j * 4);
            int c = cg * 12 + j * 4;
            Qs[(c + 0) * 32 + r] = v.x * SCALE;
            Qs[(c + 1) * 32 + r] = v.y * SCALE;
            Qs[(c + 2) * 32 + r] = v.z * SCALE;
            Qs[(c + 3) * 32 + r] = v.w * SCALE;
        }
    }
    // ---- load bias tables for the 32 q rows ----
    for (int i = tid; i < 32 * 14; i += 256) {
        int r = i / 14, kh = i - r * 14;
        size_t base = ((size_t)bh * NTOK + qbase + r);
        bhs[i] = g_relh[base * 14 + kh];
        bws[i] = g_relw[base * 14 + kh];
    }
    if (tid < 32 * 8) {
        int r = tid >> 3, kt = tid & 7;
        bts[tid] = g_relt[((size_t)bh * NTOK + qbase + r) * 8 + kt];
    }

    float m[2] = {-1e30f, -1e30f};
    float l[2] = {0.f, 0.f};
    float o[2][6];
#pragma unroll
    for (int j = 0; j < 2; j++)
#pragma unroll
        for (int i = 0; i < 6; i++) o[j][i] = 0.f;

    for (int kc = 0; kc < 25; kc++) {
        const int kb = kc * TK;
        __syncthreads();   // protect Ks/Vs/Ps from previous iteration readers

        // ---- load K tile (transposed) and V tile ----
        {
            int r = tid & 63;
            int cg = tid >> 6;    // 0..3 -> 24 cols
            int gk = kb + r;
            bool ok = gk < NTOK;
            const float* ks = kptr + (size_t)gk * HD + cg * 24;
            const float* vs = vptr + (size_t)gk * HD + cg * 24;
#pragma unroll
            for (int j = 0; j < 6; j++) {
                int c = cg * 24 + j * 4;
                float4 a = ok ? *(const float4*)(ks + j * 4) : make_float4(0,0,0,0);
                Ks[(c + 0) * 64 + r] = a.x;
                Ks[(c + 1) * 64 + r] = a.y;
                Ks[(c + 2) * 64 + r] = a.z;
                Ks[(c + 3) * 64 + r] = a.w;
                float4 b = ok ? *(const float4*)(vs + j * 4) : make_float4(0,0,0,0);
                *(float4*)&Vs[r * 100 + c] = b;
            }
            if (tid < 64) {
                int gk2 = kb + tid;
                int kt = gk2 / (HH * WW); if (kt > TT - 1) kt = TT - 1;
                int rem = gk2 - kt * (HH * WW);
                kti[tid] = kt;
                khi[tid] = rem / WW < HH ? rem / WW : HH - 1;
                kwi[tid] = rem % WW;
            }
        }
        __syncthreads();

        // ---- GEMM1: S = Qs^T-scaled @ K ----
        float acc[2][4];
#pragma unroll
        for (int j = 0; j < 2; j++)
#pragma unroll
            for (int i = 0; i < 4; i++) acc[j][i] = 0.f;
#pragma unroll 8
        for (int kk = 0; kk < 96; kk++) {
            float2 a = *(const float2*)&Qs[kk * 32 + r0];
            float4 b = *(const float4*)&Ks[kk * 64 + c0];
            acc[0][0] += a.x * b.x; acc[0][1] += a.x * b.y;
            acc[0][2] += a.x * b.z; acc[0][3] += a.x * b.w;
            acc[1][0] += a.y * b.x; acc[1][1] += a.y * b.y;
            acc[1][2] += a.y * b.z; acc[1][3] += a.y * b.w;
        }

        // ---- bias + online softmax ----
        float p[2][4];
        float cm[2] = {-1e30f, -1e30f};
#pragma unroll
        for (int i = 0; i < 4; i++) {
            int cc = c0 + i;
            int gk = kb + cc;
            float bt0 = bts[r0 * 8 + kti[cc]]       + bhs[r0 * 14 + khi[cc]]       + bws[r0 * 14 + kwi[cc]];
            float bt1 = bts[(r0 + 1) * 8 + kti[cc]] + bhs[(r0 + 1) * 14 + khi[cc]] + bws[(r0 + 1) * 14 + kwi[cc]];
            float s0 = acc[0][i] + bt0;
            float s1 = acc[1][i] + bt1;
            if (gk >= NTOK) { s0 = -1e30f; s1 = -1e30f; }
            p[0][i] = s0; p[1][i] = s1;
            cm[0] = fmaxf(cm[0], s0);
            cm[1] = fmaxf(cm[1], s1);
        }
#pragma unroll
        for (int off = 1; off < 16; off <<= 1) {
            cm[0] = fmaxf(cm[0], __shfl_xor_sync(0xffffffffu, cm[0], off));
            cm[1] = fmaxf(cm[1], __shfl_xor_sync(0xffffffffu, cm[1], off));
        }
        float rs[2] = {0.f, 0.f};
#pragma unroll
        for (int j = 0; j < 2; j++) {
            float mn = fmaxf(m[j], cm[j]);
            float f = __expf(m[j] - mn);
            m[j] = mn;
#pragma unroll
            for (int i = 0; i < 4; i++) {
                p[j][i] = __expf(p[j][i] - mn);
                rs[j] += p[j][i];
            }
            l[j] *= f;
#pragma unroll
            for (int i = 0; i < 6; i++) o[j][i] *= f;
        }
#pragma unroll
        for (int off = 1; off < 16; off <<= 1) {
            rs[0] += __shfl_xor_sync(0xffffffffu, rs[0], off);
            rs[1] += __shfl_xor_sync(0xffffffffu, rs[1], off);
        }
        l[0] += rs[0]; l[1] += rs[1];

        *(float4*)&Ps[r0 * 68 + c0]       = make_float4(p[0][0], p[0][1], p[0][2], p[0][3]);
        *(float4*)&Ps[(r0 + 1) * 68 + c0] = make_float4(p[1][0], p[1][1], p[1][2], p[1][3]);
        __syncthreads();

        // ---- GEMM2: O += P @ V ----
#pragma unroll 8
        for (int kk = 0; kk < TK; kk++) {
            float p0 = Ps[r0 * 68 + kk];
            float p1 = Ps[(r0 + 1) * 68 + kk];
            const float* vrow = &Vs[kk * 100 + vc];
            float2 va = *(const float2*)(vrow);
            float2 vb = *(const float2*)(vrow + 2);
            float2 vx = *(const float2*)(vrow + 4);
            o[0][0] += p0 * va.x; o[0][1] += p0 * va.y;
            o[0][2] += p0 * vb.x; o[0][3] += p0 * vb.y;
            o[0][4] += p0 * vx.x; o[0][5] += p0 * vx.y;
            o[1][0] += p1 * va.x; o[1][1] += p1 * va.y;
            o[1][2] += p1 * vb.x; o[1][3] += p1 * vb.y;
            o[1][4] += p1 * vx.x; o[1][5] += p1 * vx.y;
        }
    }

    // ---- epilogue: /l, + residual pooled q, scatter to [B][N][NH][HD] ----
    const int b = bh >> 2, head = bh & 3;
#pragma unroll
    for (int j = 0; j < 2; j++) {
        int qn = qbase + r0 + j;
        float inv = 1.0f / l[j];
        float* dst = g_ctx + (((size_t)(b * NTOK + qn)) * NHD + head) * HD + vc;
        const float* qr = qptr + (size_t)qn * HD + vc;
#pragma unroll
        for (int i = 0; i < 6; i++) dst[i] = o[j][i] * inv + qr[i];
    }
}

// ---------------------------------------------------------------------------
// launch
// ---------------------------------------------------------------------------
extern "C" void kernel_launch(void* const* d_in, const int* in_sizes, int n_in,
                              void* d_out, int out_size)
{
    (void)in_sizes; (void)n_in; (void)out_size;
    const float* x      = (const float*)d_in[0];
    const float* qkv_w  = (const float*)d_in[1];
    const float* proj_w = (const float*)d_in[2];
    const float* proj_b = (const float*)d_in[3];
    const float* pqw    = (const float*)d_in[4];
    const float* pkw    = (const float*)d_in[5];
    const float* pvw    = (const float*)d_in[6];
    const float* nqw    = (const float*)d_in[7];
    const float* nqb    = (const float*)d_in[8];
    const float* nkw    = (const float*)d_in[9];
    const float* nkb    = (const float*)d_in[10];
    const float* nvw    = (const float*)d_in[11];
    const float* nvb    = (const float*)d_in[12];
    const float* rph    = (const float*)d_in[13];
    const float* rpw    = (const float*)d_in[14];
    const float* rpt    = (const float*)d_in[15];
    float* out = (float*)d_out;

    cudaFuncSetAttribute(attn_kernel, cudaFuncAttributeMaxDynamicSharedMemorySize,
                         ATTN_SMEM_BYTES);

    const int M = BQ * NTOK;  // 3136
    // K1: QKV projection, scatter to q0/k0/v0
    sgemm_kernel<0><<<dim3((M + GBM - 1) / GBM, (3 * DIMV) / GBN), 256>>>(
        x, qkv_w, nullptr, nullptr, M, 3 * DIMV, DIMV);
    // K2: depthwise conv3d + LN for q, k, v
    pool_ln_kernel<<<dim3(BH * NTOK, 3), 96>>>(pqw, pkw, pvw,
                                               nqw, nqb, nkw, nkb, nvw, nvb);
    // K3: rel-pos bias dots
    relbias_kernel<<<BH * NTOK, 128>>>(rph, rpw, rpt);
    // K4: flash attention with bias + residual
    attn_kernel<<<dim3(NTOK / TQ, BH), 256, ATTN_SMEM_BYTES>>>();
    // K5: output projection
    sgemm_kernel<1><<<dim3((M + GBM - 1) / GBM, DIMV / GBN), 256>>>(
        nullptr, proj_w, proj_b, out, M, DIMV, DIMV);
}